// round 1
// baseline (speedup 1.0000x reference)
#include <cuda_runtime.h>
#include <cuda_bf16.h>

// Problem constants (fixed shapes from reference):
//   x1: [75, 441, 64] f32
//   x2: [1, 5, 5, 441, 64] f32 -> domain 0 -> [25, 441, 64]
//   out: [75, 25] f32
#define NB 75      // query rows
#define NS 25      // support rows
#define HW 441     // spatial positions
#define C  64      // channels
#define NROWS (NB + NS)  // 100

// Scratch: normalized-sum descriptors, [100][64]
__device__ float g_bar[NROWS * C];

// Kernel 1: for each row r (query b or support s), compute
//   bar[r][c] = sum_j x[r][j][c] / ||x[r][j][:]||
// One CTA per row, 16 warps; warp w handles j = w, w+16, ...
// Each lane owns channels (2*lane, 2*lane+1) via float2 loads (fully coalesced).
__global__ __launch_bounds__(512) void normalize_sum_kernel(
    const float* __restrict__ x1, const float* __restrict__ x2)
{
    const int r = blockIdx.x;                  // 0..99
    const float* base = (r < NB)
        ? (x1 + (size_t)r * (HW * C))
        : (x2 + (size_t)(r - NB) * (HW * C));  // x2[0] is contiguous [25,441,64]

    const int warp = threadIdx.x >> 5;
    const int lane = threadIdx.x & 31;

    float accx = 0.0f, accy = 0.0f;

    #pragma unroll 4
    for (int j = warp; j < HW; j += 16) {
        float2 v = reinterpret_cast<const float2*>(base + j * C)[lane];
        float ss = v.x * v.x + v.y * v.y;
        // warp-wide sum of squares (64 values)
        #pragma unroll
        for (int o = 16; o; o >>= 1)
            ss += __shfl_xor_sync(0xffffffffu, ss, o);
        // rsqrt + one Newton step -> ~fp32-exact 1/||.||
        float inv = rsqrtf(ss);
        inv = inv * (1.5f - 0.5f * ss * inv * inv);
        accx = fmaf(v.x, inv, accx);
        accy = fmaf(v.y, inv, accy);
    }

    __shared__ float2 sh[16][32];
    sh[warp][lane] = make_float2(accx, accy);
    __syncthreads();

    if (warp == 0) {
        float sx = 0.0f, sy = 0.0f;
        #pragma unroll
        for (int w = 0; w < 16; w++) {
            sx += sh[w][lane].x;
            sy += sh[w][lane].y;
        }
        g_bar[r * C + 2 * lane]     = sx;
        g_bar[r * C + 2 * lane + 1] = sy;
    }
}

// Kernel 2: out[b][s] = dot(g_bar[b], g_bar[75+s]) over C=64.
// 75 CTAs x 128 threads; warp w handles s = w, w+4, ...
__global__ __launch_bounds__(128) void small_gemm_kernel(float* __restrict__ out)
{
    const int b = blockIdx.x;                  // 0..74
    __shared__ float q[C];
    if (threadIdx.x < C) q[threadIdx.x] = g_bar[b * C + threadIdx.x];
    __syncthreads();

    const int warp = threadIdx.x >> 5;
    const int lane = threadIdx.x & 31;

    for (int s = warp; s < NS; s += 4) {
        float2 sv = reinterpret_cast<const float2*>(g_bar + (NB + s) * C)[lane];
        float p = q[2 * lane] * sv.x + q[2 * lane + 1] * sv.y;
        #pragma unroll
        for (int o = 16; o; o >>= 1)
            p += __shfl_xor_sync(0xffffffffu, p, o);
        if (lane == 0) out[b * NS + s] = p;
    }
}

extern "C" void kernel_launch(void* const* d_in, const int* in_sizes, int n_in,
                              void* d_out, int out_size)
{
    const float* x1 = (const float*)d_in[0];   // [75,441,64]
    const float* x2 = (const float*)d_in[1];   // [1,5,5,441,64]
    float* out = (float*)d_out;                // [75,25]

    normalize_sum_kernel<<<NROWS, 512>>>(x1, x2);
    small_gemm_kernel<<<NB, 128>>>(out);
}

// round 2
// speedup vs baseline: 1.0025x; 1.0025x over previous
#include <cuda_runtime.h>
#include <cuda_bf16.h>

// Shapes (fixed):
//   x1: [75, 441, 64] f32  (queries)
//   x2: [1, 5, 5, 441, 64] f32 -> domain 0 -> [25, 441, 64] (support)
//   out: [75, 25] f32
#define NB 75
#define NS 25
#define HW 441
#define C  64
#define NROWS (NB + NS)   // 100 CTAs, all co-resident on 148 SMs (spin is safe)

// Support normalized-sum descriptors [25][64] + handshake counters.
__device__ float        g_sbar[NS * C];
__device__ unsigned int g_scount;   // support rows completed (release/acquire)
__device__ unsigned int g_qdone;    // query CTAs finished (for counter reset)

__global__ __launch_bounds__(512) void fused_img2class_kernel(
    const float* __restrict__ x1, const float* __restrict__ x2,
    float* __restrict__ out)
{
    const int r = blockIdx.x;                 // 0..99; first 25 = support
    const bool is_support = (r < NS);
    const float* base = is_support
        ? (x2 + (size_t)r * (HW * C))         // x2[0] contiguous [25,441,64]
        : (x1 + (size_t)(r - NS) * (HW * C));

    const int warp = threadIdx.x >> 5;
    const int lane = threadIdx.x & 31;

    // ---- Phase 1: bar[c] = sum_j x[j][c] / ||x[j][:]|| ----
    // 16 warps; warp w handles j = w, w+16, ... Lane owns channels (2l, 2l+1).
    float accx = 0.0f, accy = 0.0f;
    #pragma unroll 4
    for (int j = warp; j < HW; j += 16) {
        float2 v = reinterpret_cast<const float2*>(base + j * C)[lane];
        float ss = v.x * v.x + v.y * v.y;
        #pragma unroll
        for (int o = 16; o; o >>= 1)
            ss += __shfl_xor_sync(0xffffffffu, ss, o);
        float inv = rsqrtf(ss);
        inv = inv * (1.5f - 0.5f * ss * inv * inv);   // Newton step
        accx = fmaf(v.x, inv, accx);
        accy = fmaf(v.y, inv, accy);
    }

    __shared__ float2 sh[16][32];
    __shared__ float  shq[C];
    sh[warp][lane] = make_float2(accx, accy);
    __syncthreads();

    if (warp == 0) {
        float sx = 0.0f, sy = 0.0f;
        #pragma unroll
        for (int w = 0; w < 16; w++) { sx += sh[w][lane].x; sy += sh[w][lane].y; }
        if (is_support) {
            g_sbar[r * C + 2 * lane]     = sx;
            g_sbar[r * C + 2 * lane + 1] = sy;
        } else {
            shq[2 * lane]     = sx;
            shq[2 * lane + 1] = sy;
        }
    }
    __syncthreads();

    if (is_support) {
        // Publish: all g_sbar writes (done before the syncthreads above) ->
        // fence -> release-increment of the counter.
        if (threadIdx.x == 0) {
            __threadfence();
            asm volatile("red.release.gpu.add.u32 [%0], 1;"
                         :: "l"(&g_scount) : "memory");
        }
        return;
    }

    // ---- Phase 2 (queries): wait for all 25 support rows ----
    if (threadIdx.x == 0) {
        unsigned int v;
        do {
            asm volatile("ld.acquire.gpu.u32 %0, [%1];"
                         : "=r"(v) : "l"(&g_scount) : "memory");
            if (v < NS) __nanosleep(64);
        } while (v < NS);
    }
    __syncthreads();   // broadcast acquire to all threads in CTA

    // ---- Epilogue: out[b][s] = dot(q_bar, s_bar[s]) over C=64 ----
    const int b = r - NS;
    for (int s = warp; s < NS; s += 16) {      // warps 0..8 do two s values
        float2 sv = reinterpret_cast<const float2*>(g_sbar + s * C)[lane];
        float p = shq[2 * lane] * sv.x + shq[2 * lane + 1] * sv.y;
        #pragma unroll
        for (int o = 16; o; o >>= 1)
            p += __shfl_xor_sync(0xffffffffu, p, o);
        if (lane == 0) out[b * NS + s] = p;
    }

    // ---- Reset counters for the next graph replay (deterministic) ----
    __syncthreads();
    if (threadIdx.x == 0) {
        unsigned int old = atomicAdd(&g_qdone, 1u);
        if (old == NB - 1) {        // last query CTA; nobody reads these again
            g_scount = 0u;          // this launch
            g_qdone  = 0u;
        }
    }
}

extern "C" void kernel_launch(void* const* d_in, const int* in_sizes, int n_in,
                              void* d_out, int out_size)
{
    const float* x1 = (const float*)d_in[0];   // [75,441,64]
    const float* x2 = (const float*)d_in[1];   // [1,5,5,441,64]
    float* out = (float*)d_out;                // [75,25]

    fused_img2class_kernel<<<NROWS, 512>>>(x1, x2, out);
}

// round 5
// speedup vs baseline: 1.2143x; 1.2113x over previous
#include <cuda_runtime.h>
#include <cuda_bf16.h>

// Shapes (fixed):
//   x1: [75, 441, 64] f32  (queries)
//   x2: [1, 5, 5, 441, 64] f32 -> domain 0 -> [25, 441, 64] (support)
//   out: [75, 25] f32
#define NB 75
#define NS 25
#define HW 441
#define C  64
#define NROWS (NB + NS)   // 100 CTAs <= 148 SMs: all co-resident, spin is safe

#define RS 68                          // padded row stride in words (16B aligned, conflict-free)
#define BUF_WORDS (HW * RS)            // 29988
#define SMEM_WORDS (BUF_WORDS + HW)    // + inv[441]
#define SMEM_BYTES (SMEM_WORDS * 4)    // 121716 B

// Support normalized-sum descriptors [25][64] + handshake counters.
__device__ float        g_sbar[NS * C];
__device__ unsigned int g_scount;   // support rows completed (release/acquire)
__device__ unsigned int g_qdone;    // query CTAs finished (for counter reset)

__global__ __launch_bounds__(512, 1) void fused_img2class_kernel(
    const float* __restrict__ x1, const float* __restrict__ x2,
    float* __restrict__ out)
{
    extern __shared__ float sbuf[];          // [441*68] row data + [441] inv norms
    float* invn = sbuf + BUF_WORDS;
    __shared__ float2 shred[16][32];
    __shared__ float  shq[C];

    const int r = blockIdx.x;                // 0..99; first 25 = support
    const bool is_support = (r < NS);
    const float* base = is_support
        ? (x2 + (size_t)r * (HW * C))        // x2[0] contiguous [25,441,64]
        : (x1 + (size_t)(r - NS) * (HW * C));

    const int tid  = threadIdx.x;
    const int warp = tid >> 5;
    const int lane = tid & 31;

    // ---- Phase 1: stage whole row to SMEM (coalesced float4, high MLP) ----
    // Global float4 index f = j*16 + i  ->  SMEM float4 index j*17 + i (stride 68 words).
    {
        const float4* gsrc = reinterpret_cast<const float4*>(base);
        float4* sdst = reinterpret_cast<float4*>(sbuf);
        #pragma unroll 4
        for (int f = tid; f < HW * 16; f += 512) {
            int j = f >> 4, i = f & 15;
            sdst[j * 17 + i] = gsrc[f];
        }
    }
    __syncthreads();

    // ---- Phase 2: per-position inverse norms, one thread per j, no shuffles ----
    if (tid < HW) {
        const float4* row = reinterpret_cast<const float4*>(sbuf) + tid * 17;
        float s0 = 0.f, s1 = 0.f, s2 = 0.f, s3 = 0.f;
        #pragma unroll
        for (int i = 0; i < 16; i += 4) {
            float4 a = row[i + 0]; s0 += a.x*a.x + a.y*a.y + a.z*a.z + a.w*a.w;
            float4 b = row[i + 1]; s1 += b.x*b.x + b.y*b.y + b.z*b.z + b.w*b.w;
            float4 c = row[i + 2]; s2 += c.x*c.x + c.y*c.y + c.z*c.z + c.w*c.w;
            float4 d = row[i + 3]; s3 += d.x*d.x + d.y*d.y + d.z*d.z + d.w*d.w;
        }
        float ss = (s0 + s1) + (s2 + s3);
        float iv = rsqrtf(ss);
        iv = iv * (1.5f - 0.5f * ss * iv * iv);   // Newton step -> fp32-exact
        invn[tid] = iv;
    }
    __syncthreads();

    // ---- Phase 3: bar[c] = sum_j x[j][c] * inv[j]  (pure LDS + FFMA) ----
    float accx = 0.f, accy = 0.f;
    #pragma unroll 4
    for (int j = warp; j < HW; j += 16) {
        float2 v = *reinterpret_cast<const float2*>(sbuf + j * RS + 2 * lane);
        float iv = invn[j];                       // broadcast LDS
        accx = fmaf(v.x, iv, accx);
        accy = fmaf(v.y, iv, accy);
    }

    shred[warp][lane] = make_float2(accx, accy);
    __syncthreads();

    if (warp == 0) {
        float sx = 0.f, sy = 0.f;
        #pragma unroll
        for (int w = 0; w < 16; w++) { sx += shred[w][lane].x; sy += shred[w][lane].y; }
        if (is_support) {
            g_sbar[r * C + 2 * lane]     = sx;
            g_sbar[r * C + 2 * lane + 1] = sy;
        } else {
            shq[2 * lane]     = sx;
            shq[2 * lane + 1] = sy;
        }
    }
    __syncthreads();

    if (is_support) {
        if (tid == 0) {
            __threadfence();
            asm volatile("red.release.gpu.add.u32 [%0], 1;"
                         :: "l"(&g_scount) : "memory");
        }
        return;
    }

    // ---- Queries: wait for all 25 support rows ----
    if (tid == 0) {
        unsigned int v;
        do {
            asm volatile("ld.acquire.gpu.u32 %0, [%1];"
                         : "=r"(v) : "l"(&g_scount) : "memory");
            if (v < NS) __nanosleep(64);
        } while (v < NS);
    }
    __syncthreads();   // broadcast acquire to the CTA

    // ---- Epilogue: out[b][s] = dot(q_bar, s_bar[s]) over C=64 ----
    const int b = r - NS;
    for (int s = warp; s < NS; s += 16) {
        float2 sv = reinterpret_cast<const float2*>(g_sbar + s * C)[lane];
        float p = shq[2 * lane] * sv.x + shq[2 * lane + 1] * sv.y;
        #pragma unroll
        for (int o = 16; o; o >>= 1)
            p += __shfl_xor_sync(0xffffffffu, p, o);
        if (lane == 0) out[b * NS + s] = p;
    }

    // ---- Reset counters for the next graph replay ----
    __syncthreads();
    if (tid == 0) {
        unsigned int old = atomicAdd(&g_qdone, 1u);
        if (old == NB - 1) {
            g_scount = 0u;
            g_qdone  = 0u;
        }
    }
}

extern "C" void kernel_launch(void* const* d_in, const int* in_sizes, int n_in,
                              void* d_out, int out_size)
{
    const float* x1 = (const float*)d_in[0];   // [75,441,64]
    const float* x2 = (const float*)d_in[1];   // [1,5,5,441,64]
    float* out = (float*)d_out;                // [75,25]

    // Sticky per-function attribute; safe to set every call (applied by the
    // uncaptured correctness call before graph capture happens).
    cudaFuncSetAttribute(fused_img2class_kernel,
                         cudaFuncAttributeMaxDynamicSharedMemorySize, SMEM_BYTES);

    fused_img2class_kernel<<<NROWS, 512, SMEM_BYTES>>>(x1, x2, out);
}

// round 6
// speedup vs baseline: 1.5000x; 1.2353x over previous
#include <cuda_runtime.h>
#include <cuda_bf16.h>

// Shapes (fixed):
//   x1: [75, 441, 64] f32  (queries)
//   x2: [1, 5, 5, 441, 64] f32 -> domain 0 -> [25, 441, 64] (support)
//   out: [75, 25] f32
#define NB 75
#define NS 25
#define HW 441
#define C  64
#define NROWS (NB + NS)   // 100 CTAs <= 148 SMs: all co-resident, spin is safe
#define NF4 (HW * 16)     // 7056 float4 per row
#define NK 14             // ceil(7056/512); k=13 valid only for tid<400
#define TAIL 400          // 7056 - 13*512 (multiple of 16 -> lane groups intact)
#define PS 68             // partial-array row stride (words), 16B-aligned

// Support normalized-sum descriptors [25][64] + handshake counters.
__device__ float        g_sbar[NS * C];
__device__ unsigned int g_scount;   // support rows completed (release/acquire)
__device__ unsigned int g_qdone;    // query CTAs finished (for counter reset)

__global__ __launch_bounds__(512, 1) void fused_img2class_kernel(
    const float* __restrict__ x1, const float* __restrict__ x2,
    float* __restrict__ out)
{
    __shared__ float partial[32 * PS];   // [group 0..31][channel 0..63] padded
    __shared__ float shq[C];

    const int r = blockIdx.x;                // 0..99; first 25 = support
    const bool is_support = (r < NS);
    const float* base = is_support
        ? (x2 + (size_t)r * (HW * C))        // x2[0] contiguous [25,441,64]
        : (x1 + (size_t)(r - NS) * (HW * C));

    const int tid = threadIdx.x;

    // ---- Phase 1: all 14 LDG.128 upfront (MLP=14/thread, coalesced 512B/warp)
    // f = 512k + tid:  j = f>>4 = 32k + tid/16 ; channel block = (tid&15)*4.
    // For fixed k, row j's 16 float4s sit in 16 consecutive lanes of one warp.
    const float4* g = reinterpret_cast<const float4*>(base);
    const bool vtail = (tid < TAIL);
    float4 d[NK];
    #pragma unroll
    for (int k = 0; k < NK - 1; k++)
        d[k] = g[512 * k + tid];
    d[NK - 1] = vtail ? g[512 * (NK - 1) + tid] : make_float4(0.f, 0.f, 0.f, 0.f);

    // ---- Phase 2: per-row inverse norms via 16-lane shfl groups -------------
    float inv[NK];
    #pragma unroll
    for (int k = 0; k < NK; k++) {
        float4 a = d[k];
        float ss = a.x * a.x + a.y * a.y + a.z * a.z + a.w * a.w;
        ss += __shfl_xor_sync(0xffffffffu, ss, 1);
        ss += __shfl_xor_sync(0xffffffffu, ss, 2);
        ss += __shfl_xor_sync(0xffffffffu, ss, 4);
        ss += __shfl_xor_sync(0xffffffffu, ss, 8);   // 16-lane group sum
        float iv = rsqrtf(ss);
        iv = iv * (1.5f - 0.5f * ss * iv * iv);      // Newton -> fp32-exact
        inv[k] = iv;
    }
    if (!vtail) inv[NK - 1] = 0.f;    // kill 0*inf -> NaN on invalid lanes

    // ---- Phase 3: register accumulation of bar over this thread's 14 j's ----
    float bx = 0.f, by = 0.f, bz = 0.f, bw = 0.f;
    #pragma unroll
    for (int k = 0; k < NK; k++) {
        bx = fmaf(d[k].x, inv[k], bx);
        by = fmaf(d[k].y, inv[k], by);
        bz = fmaf(d[k].z, inv[k], bz);
        bw = fmaf(d[k].w, inv[k], bw);
    }

    // ---- Phase 4: cross-group reduce (32 partials per channel) --------------
    {
        const int grp = tid >> 4;            // 0..31
        const int cb  = (tid & 15) * 4;      // channel block
        *reinterpret_cast<float4*>(&partial[grp * PS + cb]) =
            make_float4(bx, by, bz, bw);
    }
    __syncthreads();

    if (tid < C) {
        float s = 0.f;
        #pragma unroll
        for (int gix = 0; gix < 32; gix++)
            s += partial[gix * PS + tid];
        if (is_support) g_sbar[r * C + tid] = s;
        else            shq[tid] = s;
    }
    __syncthreads();

    if (is_support) {
        if (tid == 0) {
            __threadfence();
            asm volatile("red.release.gpu.add.u32 [%0], 1;"
                         :: "l"(&g_scount) : "memory");
        }
        return;
    }

    // ---- Queries: wait for all 25 support rows ------------------------------
    if (tid == 0) {
        unsigned int v;
        do {
            asm volatile("ld.acquire.gpu.u32 %0, [%1];"
                         : "=r"(v) : "l"(&g_scount) : "memory");
            if (v < NS) __nanosleep(64);
        } while (v < NS);
    }
    __syncthreads();   // broadcast acquire to the CTA

    // ---- Epilogue: out[b][s] = dot(q_bar, s_bar[s]) over C=64 ---------------
    const int b    = r - NS;
    const int warp = tid >> 5;
    const int lane = tid & 31;
    for (int s = warp; s < NS; s += 16) {
        float2 sv = reinterpret_cast<const float2*>(g_sbar + s * C)[lane];
        float p = shq[2 * lane] * sv.x + shq[2 * lane + 1] * sv.y;
        #pragma unroll
        for (int o = 16; o; o >>= 1)
            p += __shfl_xor_sync(0xffffffffu, p, o);
        if (lane == 0) out[b * NS + s] = p;
    }

    // ---- Reset counters for the next graph replay ---------------------------
    __syncthreads();
    if (tid == 0) {
        unsigned int old = atomicAdd(&g_qdone, 1u);
        if (old == NB - 1) {
            g_scount = 0u;
            g_qdone  = 0u;
        }
    }
}

extern "C" void kernel_launch(void* const* d_in, const int* in_sizes, int n_in,
                              void* d_out, int out_size)
{
    const float* x1 = (const float*)d_in[0];   // [75,441,64]
    const float* x2 = (const float*)d_in[1];   // [1,5,5,441,64]
    float* out = (float*)d_out;                // [75,25]

    fused_img2class_kernel<<<NROWS, 512>>>(x1, x2, out);
}